// round 16
// baseline (speedup 1.0000x reference)
#include <cuda_runtime.h>
#include <cuda_fp16.h>

// Problem constants (fixed by the reference)
#define VV   4096                 // vocab
#define MM   4                    // markov order
#define BB   8
#define LL   2048
#define FAN  (MM * (VV + 1))      // 16388
#define NPOS (BB * LL)            // 16384

#define TPB  1024                 // 32 warps -> occ ~49% at 1 CTA/SM
#define SMEM_BYTES (FAN * 4 * 2)  // __half table [FAN][4] = 131104 B

// ---------------------------------------------------------------------------
// Fused table-in-SMEM kernel, v2. One block per vocab quad (grid = 1024).
//  Phase 1: read W rows v0..v0+3 (coalesced, each W byte read once
//    chip-wide), quantize fp16, store interleaved [FAN][4] (STS.64,
//    contiguous per warp -> conflict-free).
//  Phase 2: 32 warps sweep all positions, TWO positions per thread per
//    iteration (8 independent LDS.64 + 2 STG.128 in flight) to cover the
//    random-bank smem latency. Pairwise HADD2, exact fp32 bias, __stcs.
// Adjacent blocks (adjacent vocab quads) run concurrently -> their 16 B
// halves of each 32 B output sector merge in L2 (verified in R14: total
// DRAM ~= compulsory 524 MB).
// ---------------------------------------------------------------------------
__global__ __launch_bounds__(TPB, 1)
void ngram_fused_smem(const float* __restrict__ W,
                      const float* __restrict__ bias,
                      const int*   __restrict__ idx,
                      float*       __restrict__ out) {
    extern __shared__ __half s_tab[];      // [FAN][4] interleaved

    const int v0 = blockIdx.x * 4;
    const int t  = threadIdx.x;

    // ---- Phase 1: load + quantize -----------------------------------------
    {
        const float* w0 = W + (size_t)(v0 + 0) * FAN;
        const float* w1 = W + (size_t)(v0 + 1) * FAN;
        const float* w2 = W + (size_t)(v0 + 2) * FAN;
        const float* w3 = W + (size_t)(v0 + 3) * FAN;
        for (int i = t; i < FAN; i += TPB) {
            const float x0 = __ldcs(w0 + i);
            const float x1 = __ldcs(w1 + i);
            const float x2 = __ldcs(w2 + i);
            const float x3 = __ldcs(w3 + i);
            const __half2 p0 = __floats2half2_rn(x0, x1);
            const __half2 p1 = __floats2half2_rn(x2, x3);
            uint2 o;
            o.x = *reinterpret_cast<const unsigned int*>(&p0);
            o.y = *reinterpret_cast<const unsigned int*>(&p1);
            *reinterpret_cast<uint2*>(&s_tab[i * 4]) = o;   // contiguous STS.64
        }
    }

    const float4 bb = *reinterpret_cast<const float4*>(&bias[v0]);

    __syncthreads();

    // ---- Phase 2: gather, 2 positions per thread per iteration -------------
    // NPOS / TPB = 16 positions per thread = 8 iterations x 2.
    #pragma unroll
    for (int it = 0; it < NPOS / TPB / 2; it++) {
        const int pA = t + (2 * it) * TPB;
        const int pB = pA + TPB;

        // --- tokens for both positions (idx is L1-resident after warm-up) ---
        const int lA = pA & (LL - 1), bA = pA >> 11, baseA = bA * LL + lA;
        const int lB = pB & (LL - 1), bB = pB >> 11, baseB = bB * LL + lB;

        const int a0t = (lA >= 3) ? __ldg(&idx[baseA - 3]) : VV;
        const int a1t = (lA >= 2) ? __ldg(&idx[baseA - 2]) : VV;
        const int a2t = (lA >= 1) ? __ldg(&idx[baseA - 1]) : VV;
        const int a3t = __ldg(&idx[baseA]);
        const int b0t = (lB >= 3) ? __ldg(&idx[baseB - 3]) : VV;
        const int b1t = (lB >= 2) ? __ldg(&idx[baseB - 2]) : VV;
        const int b2t = (lB >= 1) ? __ldg(&idx[baseB - 1]) : VV;
        const int b3t = __ldg(&idx[baseB]);

        // --- 8 independent random-row LDS.64 --------------------------------
        const uint2 a0 = *reinterpret_cast<const uint2*>(&s_tab[(0 * (VV + 1) + a0t) * 4]);
        const uint2 a1 = *reinterpret_cast<const uint2*>(&s_tab[(1 * (VV + 1) + a1t) * 4]);
        const uint2 a2 = *reinterpret_cast<const uint2*>(&s_tab[(2 * (VV + 1) + a2t) * 4]);
        const uint2 a3 = *reinterpret_cast<const uint2*>(&s_tab[(3 * (VV + 1) + a3t) * 4]);
        const uint2 c0 = *reinterpret_cast<const uint2*>(&s_tab[(0 * (VV + 1) + b0t) * 4]);
        const uint2 c1 = *reinterpret_cast<const uint2*>(&s_tab[(1 * (VV + 1) + b1t) * 4]);
        const uint2 c2 = *reinterpret_cast<const uint2*>(&s_tab[(2 * (VV + 1) + b2t) * 4]);
        const uint2 c3 = *reinterpret_cast<const uint2*>(&s_tab[(3 * (VV + 1) + b3t) * 4]);

        // --- position A: pairwise HADD2, fp32 finish + bias -----------------
        {
            const __half2 l01 = __hadd2(*reinterpret_cast<const __half2*>(&a0.x),
                                        *reinterpret_cast<const __half2*>(&a1.x));
            const __half2 l23 = __hadd2(*reinterpret_cast<const __half2*>(&a2.x),
                                        *reinterpret_cast<const __half2*>(&a3.x));
            const __half2 h01 = __hadd2(*reinterpret_cast<const __half2*>(&a0.y),
                                        *reinterpret_cast<const __half2*>(&a1.y));
            const __half2 h23 = __hadd2(*reinterpret_cast<const __half2*>(&a2.y),
                                        *reinterpret_cast<const __half2*>(&a3.y));
            const float2 fl0 = __half22float2(l01);
            const float2 fl1 = __half22float2(l23);
            const float2 fh0 = __half22float2(h01);
            const float2 fh1 = __half22float2(h23);
            float4 r;
            r.x = bb.x + (fl0.x + fl1.x);
            r.y = bb.y + (fl0.y + fl1.y);
            r.z = bb.z + (fh0.x + fh1.x);
            r.w = bb.w + (fh0.y + fh1.y);
            __stcs(reinterpret_cast<float4*>(&out[(size_t)pA * VV + v0]), r);
        }
        // --- position B -----------------------------------------------------
        {
            const __half2 l01 = __hadd2(*reinterpret_cast<const __half2*>(&c0.x),
                                        *reinterpret_cast<const __half2*>(&c1.x));
            const __half2 l23 = __hadd2(*reinterpret_cast<const __half2*>(&c2.x),
                                        *reinterpret_cast<const __half2*>(&c3.x));
            const __half2 h01 = __hadd2(*reinterpret_cast<const __half2*>(&c0.y),
                                        *reinterpret_cast<const __half2*>(&c1.y));
            const __half2 h23 = __hadd2(*reinterpret_cast<const __half2*>(&c2.y),
                                        *reinterpret_cast<const __half2*>(&c3.y));
            const float2 fl0 = __half22float2(l01);
            const float2 fl1 = __half22float2(l23);
            const float2 fh0 = __half22float2(h01);
            const float2 fh1 = __half22float2(h23);
            float4 r;
            r.x = bb.x + (fl0.x + fl1.x);
            r.y = bb.y + (fl0.y + fl1.y);
            r.z = bb.z + (fh0.x + fh1.x);
            r.w = bb.w + (fh0.y + fh1.y);
            __stcs(reinterpret_cast<float4*>(&out[(size_t)pB * VV + v0]), r);
        }
    }
}

// ---------------------------------------------------------------------------
// Launch: ONE kernel, grid = V/4 = 1024 blocks x 1024 threads, 131 KB smem.
// Inputs identified by element count:
//   idx : B*L = 16384 (int32), bias : V = 4096, W : V*FAN (largest)
// ---------------------------------------------------------------------------
extern "C" void kernel_launch(void* const* d_in, const int* in_sizes, int n_in,
                              void* d_out, int out_size) {
    const int*   idx  = nullptr;
    const float* W    = nullptr;
    const float* bias = nullptr;

    for (int i = 0; i < n_in; i++) {
        if (in_sizes[i] == NPOS)      idx  = (const int*)d_in[i];
        else if (in_sizes[i] == VV)   bias = (const float*)d_in[i];
        else                          W    = (const float*)d_in[i];
    }

    cudaFuncSetAttribute(ngram_fused_smem,
                         cudaFuncAttributeMaxDynamicSharedMemorySize,
                         SMEM_BYTES);

    ngram_fused_smem<<<VV / 4, TPB, SMEM_BYTES>>>(W, bias, idx, (float*)d_out);
}